// round 3
// baseline (speedup 1.0000x reference)
#include <cuda_runtime.h>
#include <cstddef>

// Butterfly n=1024, log_n=10, increasing stride, + bias. 32768 rows.
//
// R3: same algorithm as R2 (per-thread pre-permuted twiddles => zero-select
// exchange steering; stages 0-4 shfl_xor, 5-7 smem, 8-9 thread-local;
// 2-row ILP + prefetch), but the two pairs a thread owns (indices k and
// k+256) are packed into f32x2 lanes and all math uses packed
// mul.rn.f32x2 / fma.rn.f32x2 (SASS FFMA2, PTX-only). This halves FMA issue
// (80 -> 40 per iter) and halves smem exchange ops (STS.64/LDS.64).

constexpr int TPB  = 256;
constexpr int GRID = 296;

__device__ __forceinline__ double pk(float lo, float hi) {
    double d; asm("mov.b64 %0, {%1, %2};" : "=d"(d) : "f"(lo), "f"(hi)); return d;
}
__device__ __forceinline__ void upk(double d, float& lo, float& hi) {
    asm("mov.b64 {%0, %1}, %2;" : "=f"(lo), "=f"(hi) : "d"(d));
}
__device__ __forceinline__ double fma2(double a, double b, double c) {
    double d; asm("fma.rn.f32x2 %0, %1, %2, %3;" : "=d"(d) : "d"(a), "d"(b), "d"(c)); return d;
}
__device__ __forceinline__ double mul2(double a, double b) {
    double d; asm("mul.rn.f32x2 %0, %1, %2;" : "=d"(d) : "d"(a), "d"(b)); return d;
}
__device__ __forceinline__ double add2(double a, double b) {
    double d; asm("add.rn.f32x2 %0, %1, %2;" : "=d"(d) : "d"(a), "d"(b)); return d;
}

__global__ __launch_bounds__(TPB, 2)
void butterfly_kernel(const float* __restrict__ x,
                      const float* __restrict__ tw,
                      const float* __restrict__ bias,
                      float* __restrict__ out,
                      int nrows)
{
    __shared__ double buf[3][512];   // 3 exchange buffers x (256 thr x 2 rows)
    const int k = threadIdx.x;

    // ---- twiddles: load, pre-permute (steering baked in), pack (a|b) ------
    const float4* tw4 = reinterpret_cast<const float4*>(tw);
    double T0[10], T1[10], T2[10], T3[10];
#pragma unroll
    for (int j = 0; j < 10; ++j) {
        float4 t = tw4[j * 512 + k];
        float4 u = tw4[j * 512 + 256 + k];
        const bool rsw = (j <= 7) && (((k >> j) & 1) != 0);        // keep/send row swap
        const bool csw = (j >= 1) && (((k >> (j - 1)) & 1) != 0);  // input orientation
        if (rsw) { t = make_float4(t.z, t.w, t.x, t.y); u = make_float4(u.z, u.w, u.x, u.y); }
        if (csw) { t = make_float4(t.y, t.x, t.w, t.z); u = make_float4(u.y, u.x, u.w, u.z); }
        T0[j] = pk(t.x, u.x);
        T1[j] = pk(t.y, u.y);
        T2[j] = pk(t.z, u.z);
        T3[j] = pk(t.w, u.w);
    }
    const double BIAS0 = pk(bias[k],       bias[k + 256]);
    const double BIAS1 = pk(bias[k + 512], bias[k + 768]);

    const float2* x2 = reinterpret_cast<const float2*>(x);
    const int npairs = (nrows + 1) >> 1;

    int pi = blockIdx.x;
    float2 A0 = make_float2(0.f, 0.f), B0 = A0, A1 = A0, B1 = A0;
    if (pi < npairs) {
        const int r0 = 2 * pi, r1 = 2 * pi + 1;
        A0 = x2[(size_t)r0 * 512 + k];
        B0 = x2[(size_t)r0 * 512 + 256 + k];
        if (r1 < nrows) {
            A1 = x2[(size_t)r1 * 512 + k];
            B1 = x2[(size_t)r1 * 512 + 256 + k];
        }
    }

    while (pi < npairs) {
        const int npi = pi + GRID;
        float2 NA0 = make_float2(0.f, 0.f), NB0 = NA0, NA1 = NA0, NB1 = NA0;
        if (npi < npairs) {                      // prefetch next row pair
            const int r0 = 2 * npi, r1 = 2 * npi + 1;
            NA0 = x2[(size_t)r0 * 512 + k];
            NB0 = x2[(size_t)r0 * 512 + 256 + k];
            if (r1 < nrows) {
                NA1 = x2[(size_t)r1 * 512 + k];
                NB1 = x2[(size_t)r1 * 512 + 256 + k];
            }
        }

        // packed slots: P = slot0(a|b), Q = slot1(a|b) per row
        double P0 = pk(A0.x, B0.x), Q0 = pk(A0.y, B0.y);
        double P1 = pk(A1.x, B1.x), Q1 = pk(A1.y, B1.y);

#pragma unroll
        for (int j = 0; j < 8; ++j) {
            const int d = 1 << j;
            // keep -> P, send -> S   (2 FMUL2 + 2 FFMA2 per row)
            double S0 = fma2(T2[j], P0, mul2(T3[j], Q0));
            P0        = fma2(T0[j], P0, mul2(T1[j], Q0));
            double S1 = fma2(T2[j], P1, mul2(T3[j], Q1));
            P1        = fma2(T0[j], P1, mul2(T1[j], Q1));

            if (j <= 4) {
                float s0l, s0h, s1l, s1h;
                upk(S0, s0l, s0h);
                upk(S1, s1l, s1h);
                s0l = __shfl_xor_sync(0xffffffffu, s0l, d);
                s0h = __shfl_xor_sync(0xffffffffu, s0h, d);
                s1l = __shfl_xor_sync(0xffffffffu, s1l, d);
                s1h = __shfl_xor_sync(0xffffffffu, s1h, d);
                Q0 = pk(s0l, s0h);
                Q1 = pk(s1l, s1h);
            } else {
                double* B = buf[j - 5];
                B[k]       = S0;
                B[256 + k] = S1;
                __syncthreads();
                const int kx = k ^ d;
                Q0 = B[kx];
                Q1 = B[256 + kx];
            }
        }

        // stage 8 (d=256): partners are this thread's own two lanes
        // keep = (ya0|yb0), send = (ya1|yb1)
        double K0 = fma2(T0[8], P0, mul2(T1[8], Q0));
        double S0 = fma2(T2[8], P0, mul2(T3[8], Q0));
        double K1 = fma2(T0[8], P1, mul2(T1[8], Q1));
        double S1 = fma2(T2[8], P1, mul2(T3[8], Q1));

        // half-transpose: X0 = (ya0|ya1), X1 = (yb0|yb1)
        float a0, b0, a1, b1;
        upk(K0, a0, b0); upk(S0, a1, b1);
        double X0_0 = pk(a0, a1), X1_0 = pk(b0, b1);
        upk(K1, a0, b0); upk(S1, a1, b1);
        double X0_1 = pk(a0, a1), X1_1 = pk(b0, b1);

        // stage 9 (d=512) packed + bias
        double Z0_0 = add2(fma2(T0[9], X0_0, mul2(T1[9], X1_0)), BIAS0); // (za0|zb0)
        double Z1_0 = add2(fma2(T2[9], X0_0, mul2(T3[9], X1_0)), BIAS1); // (za1|zb1)
        double Z0_1 = add2(fma2(T0[9], X0_1, mul2(T1[9], X1_1)), BIAS0);
        double Z1_1 = add2(fma2(T2[9], X0_1, mul2(T3[9], X1_1)), BIAS1);

        // outputs: za0->k, zb0->k+256, za1->k+512, zb1->k+768
        const int r0 = 2 * pi, r1 = 2 * pi + 1;
        {
            float z0, z1, z2, z3;
            upk(Z0_0, z0, z1); upk(Z1_0, z2, z3);
            float* o = out + (size_t)r0 * 1024;
            o[k]       = z0;
            o[k + 256] = z1;
            o[k + 512] = z2;
            o[k + 768] = z3;
        }
        if (r1 < nrows) {
            float z0, z1, z2, z3;
            upk(Z0_1, z0, z1); upk(Z1_1, z2, z3);
            float* o = out + (size_t)r1 * 1024;
            o[k]       = z0;
            o[k + 256] = z1;
            o[k + 512] = z2;
            o[k + 768] = z3;
        }

        pi = npi;
        A0 = NA0; B0 = NB0; A1 = NA1; B1 = NB1;
    }
}

extern "C" void kernel_launch(void* const* d_in, const int* in_sizes, int n_in,
                              void* d_out, int out_size)
{
    const float* x  = nullptr;
    const float* tw = nullptr;
    const float* bs = nullptr;
    long long x_elems = 0;
    for (int i = 0; i < n_in; ++i) {
        if (in_sizes[i] == 20480)     tw = (const float*)d_in[i];
        else if (in_sizes[i] == 1024) bs = (const float*)d_in[i];
        else { x = (const float*)d_in[i]; x_elems = in_sizes[i]; }
    }
    const int nrows = (int)(x_elems / 1024);

    butterfly_kernel<<<GRID, TPB>>>(x, tw, bs, (float*)d_out, nrows);
}

// round 4
// speedup vs baseline: 1.0175x; 1.0175x over previous
#include <cuda_runtime.h>
#include <cstddef>

// Butterfly n=1024, log_n=10, increasing stride, + bias. 32768 rows.
//
// R4: 512 threads/block, ONE pair per thread (twiddle regs 80 -> 40,
// => __launch_bounds__(512,2) => 32 warps/SM, 2x occupancy vs R2/R3).
// Pre-permuted twiddles (zero-select steering), scalar FFMA (f32x2 was
// proven throughput-neutral in R3). Exchanges after stage j pair thread k
// with k^2^j:  j=0..4 shfl_xor, j=5..8 smem with MINIMAL-SCOPE named
// barriers (64/128/256/512 threads; unique ids 1..15 so no cross-stage
// aliasing). Stage-5..7 buffer reuse is ordered by the full stage-8
// barrier; stage-8 buffer is parity double-buffered. 2-row ILP + prefetch.

constexpr int TPB  = 512;
constexpr int GRID = 296;

__device__ __forceinline__ void barx(int id, int cnt) {
    asm volatile("bar.sync %0, %1;" :: "r"(id), "r"(cnt) : "memory");
}

__global__ __launch_bounds__(TPB, 2)
void butterfly_kernel(const float* __restrict__ x,
                      const float* __restrict__ tw,
                      const float* __restrict__ bias,
                      float* __restrict__ out,
                      int nrows)
{
    __shared__ float bufA[1024], bufB[1024], bufC[1024], bufD[2][1024];
    const int k = threadIdx.x;      // pair index 0..511
    const int w = k >> 5;           // warp 0..15

    // ---- twiddles: one pair per thread, steering pre-permuted -------------
    const float4* tw4 = reinterpret_cast<const float4*>(tw);
    float4 T[10];
#pragma unroll
    for (int j = 0; j < 10; ++j) {
        float4 t = tw4[j * 512 + k];
        const bool rsw = (j <= 8) && (((k >> j) & 1) != 0);        // keep/send rows
        const bool csw = (j >= 1) && (((k >> (j - 1)) & 1) != 0);  // input orientation
        if (rsw) t = make_float4(t.z, t.w, t.x, t.y);
        if (csw) t = make_float4(t.y, t.x, t.w, t.z);
        T[j] = t;
    }
    const float bias0 = bias[k];
    const float bias1 = bias[k + 512];

    const float2* x2 = reinterpret_cast<const float2*>(x);
    const int npairs = (nrows + 1) >> 1;

    int pi = blockIdx.x;
    int par = 0;
    float2 A0 = make_float2(0.f, 0.f), A1 = A0;
    if (pi < npairs) {
        const int r0 = 2 * pi, r1 = 2 * pi + 1;
        A0 = x2[(size_t)r0 * 512 + k];
        if (r1 < nrows) A1 = x2[(size_t)r1 * 512 + k];
    }

    while (pi < npairs) {
        const int npi = pi + GRID;
        float2 NA0 = make_float2(0.f, 0.f), NA1 = NA0;
        if (npi < npairs) {                       // prefetch next row pair
            const int r0 = 2 * npi, r1 = 2 * npi + 1;
            NA0 = x2[(size_t)r0 * 512 + k];
            if (r1 < nrows) NA1 = x2[(size_t)r1 * 512 + k];
        }

        float P0 = A0.x, Q0 = A0.y;   // row 0
        float P1 = A1.x, Q1 = A1.y;   // row 1

#pragma unroll
        for (int j = 0; j < 9; ++j) {
            // keep -> P, send -> S (orientation folded into twiddles)
            float S0 = fmaf(T[j].z, P0, T[j].w * Q0);
            P0       = fmaf(T[j].x, P0, T[j].y * Q0);
            float S1 = fmaf(T[j].z, P1, T[j].w * Q1);
            P1       = fmaf(T[j].x, P1, T[j].y * Q1);

            if (j <= 4) {
                const int d = 1 << j;
                Q0 = __shfl_xor_sync(0xffffffffu, S0, d);
                Q1 = __shfl_xor_sync(0xffffffffu, S1, d);
            } else if (j == 5) {
                bufA[k] = S0; bufA[512 + k] = S1;
                barx(1 + (w >> 1), 64);            // warp-pair {w, w^1}
                Q0 = bufA[k ^ 32]; Q1 = bufA[512 + (k ^ 32)];
            } else if (j == 6) {
                bufB[k] = S0; bufB[512 + k] = S1;
                barx(9 + (w >> 2), 128);           // quad {w & ~3}
                Q0 = bufB[k ^ 64]; Q1 = bufB[512 + (k ^ 64)];
            } else if (j == 7) {
                bufC[k] = S0; bufC[512 + k] = S1;
                barx(13 + (w >> 3), 256);          // octet {w & ~7}
                Q0 = bufC[k ^ 128]; Q1 = bufC[512 + (k ^ 128)];
            } else {  // j == 8
                float* D = bufD[par];
                D[k] = S0; D[512 + k] = S1;
                barx(15, 512);                     // full block
                Q0 = D[k ^ 256]; Q1 = D[512 + (k ^ 256)];
            }
        }

        // stage 9 (s=512, no exchange) + bias folded into the FMA chain
        const float z0_0 = fmaf(T[9].x, P0, fmaf(T[9].y, Q0, bias0));
        const float z1_0 = fmaf(T[9].z, P0, fmaf(T[9].w, Q0, bias1));
        const float z0_1 = fmaf(T[9].x, P1, fmaf(T[9].y, Q1, bias0));
        const float z1_1 = fmaf(T[9].z, P1, fmaf(T[9].w, Q1, bias1));

        const int r0 = 2 * pi, r1 = 2 * pi + 1;
        {
            float* o = out + (size_t)r0 * 1024;
            o[k]       = z0_0;
            o[k + 512] = z1_0;
        }
        if (r1 < nrows) {
            float* o = out + (size_t)r1 * 1024;
            o[k]       = z0_1;
            o[k + 512] = z1_1;
        }

        pi = npi;
        A0 = NA0; A1 = NA1;
        par ^= 1;
    }
}

extern "C" void kernel_launch(void* const* d_in, const int* in_sizes, int n_in,
                              void* d_out, int out_size)
{
    const float* x  = nullptr;
    const float* tw = nullptr;
    const float* bs = nullptr;
    long long x_elems = 0;
    for (int i = 0; i < n_in; ++i) {
        if (in_sizes[i] == 20480)     tw = (const float*)d_in[i];
        else if (in_sizes[i] == 1024) bs = (const float*)d_in[i];
        else { x = (const float*)d_in[i]; x_elems = in_sizes[i]; }
    }
    const int nrows = (int)(x_elems / 1024);

    butterfly_kernel<<<GRID, TPB>>>(x, tw, bs, (float*)d_out, nrows);
}